// round 2
// baseline (speedup 1.0000x reference)
#include <cuda_runtime.h>

#define N_NODES 50000
#define N_EDGES 800000
#define D 64
#define BN_EPS 1e-5f
#define NB 1184              // grid size for fused kernels (148 SMs * 8)
#define WPB 8                // warps per block
#define THREADS 256

// ---------------- scratch (static device allocations; no cudaMalloc) --------
__device__ int   g_i64;                    // 1 if edge_index is int64
__device__ int   g_rowstart[N_NODES + 1];  // CSR row offsets (keyed by dst)
__device__ int   g_cursor[N_NODES];        // scatter cursors
__device__ int   g_esrc[N_EDGES];          // CSR column indices (src nodes)
__device__ float g_y[N_NODES * D];         // pre-BN GEMM1 output
__device__ float g_partial[NB * 128];      // per-block [sum(64) | sumsq(64)]
__device__ __align__(16) float g_bnscale[D];
__device__ __align__(16) float g_bnshift[D];

// ---------------- dtype detection for edge_index ----------------------------
// If data is int64, every value < 50000 => every odd 32-bit word is 0.
// If data is int32, the odd words are src node ids; P(1024 of them all 0) ~ 0.
__global__ void detect_idx_kernel(const void* ei) {
    __shared__ int any_nonzero;
    if (threadIdx.x == 0) any_nonzero = 0;
    __syncthreads();
    const int* w = (const int*)ei;
    for (int i = threadIdx.x; i < 1024; i += blockDim.x)
        if (w[2 * i + 1] != 0) any_nonzero = 1;
    __syncthreads();
    if (threadIdx.x == 0) g_i64 = (any_nonzero == 0) ? 1 : 0;
}

__global__ void zero_deg_kernel() {
    int i = blockIdx.x * blockDim.x + threadIdx.x;
    if (i <= N_NODES) g_rowstart[i] = 0;
}

__global__ void hist_kernel(const void* ei) {
    const bool i64 = (g_i64 != 0);
    const long long* p64 = (const long long*)ei;
    const int*       p32 = (const int*)ei;
    long long stride = (long long)gridDim.x * blockDim.x;
    for (long long e = blockIdx.x * (long long)blockDim.x + threadIdx.x;
         e < N_EDGES; e += stride) {
        int d = i64 ? (int)p64[N_EDGES + e] : p32[N_EDGES + e];
        atomicAdd(&g_rowstart[d], 1);
    }
}

// One-block exclusive scan over 50000 degrees (in place), also fills cursors.
__global__ void scan_kernel() {
    constexpr int T = 1024;
    constexpr int C = (N_NODES + T - 1) / T;   // 49
    __shared__ int sm[T];
    int tid  = threadIdx.x;
    int base = tid * C;
    int local[C];
    int s = 0;
#pragma unroll
    for (int i = 0; i < C; i++) {
        int idx = base + i;
        int v = (idx < N_NODES) ? g_rowstart[idx] : 0;
        local[i] = v; s += v;
    }
    sm[tid] = s;
    __syncthreads();
    for (int off = 1; off < T; off <<= 1) {
        int add = (tid >= off) ? sm[tid - off] : 0;
        __syncthreads();
        sm[tid] += add;
        __syncthreads();
    }
    int excl = (tid == 0) ? 0 : sm[tid - 1];
#pragma unroll
    for (int i = 0; i < C; i++) {
        int idx = base + i;
        if (idx < N_NODES) {
            g_rowstart[idx] = excl;
            g_cursor[idx]   = excl;
            excl += local[i];
        }
    }
    if (tid == T - 1) g_rowstart[N_NODES] = sm[T - 1];
}

__global__ void scatter_kernel(const void* ei) {
    const bool i64 = (g_i64 != 0);
    const long long* p64 = (const long long*)ei;
    const int*       p32 = (const int*)ei;
    long long stride = (long long)gridDim.x * blockDim.x;
    for (long long e = blockIdx.x * (long long)blockDim.x + threadIdx.x;
         e < N_EDGES; e += stride) {
        int d = i64 ? (int)p64[N_EDGES + e] : p32[N_EDGES + e];
        int s = i64 ? (int)p64[e]           : p32[e];
        int pos = atomicAdd(&g_cursor[d], 1);
        g_esrc[pos] = s;
    }
}

// ---------------- K1: aggregate + x, GEMM with W1 (+b1), BN partial stats ---
// Warp-per-row: lane holds output columns (2*lane, 2*lane+1) as float2.
__global__ void __launch_bounds__(THREADS)
gin_fused1(const float* __restrict__ xin, const float* __restrict__ W1,
           const float* __restrict__ b1) {
    __shared__ float Ws[D * D];
    __shared__ float hs[WPB][D];
    __shared__ float ssum[WPB][D];
    __shared__ float ssq[WPB][D];
    int tid = threadIdx.x, w = tid >> 5, lane = tid & 31;

    for (int i = tid; i < D * D; i += THREADS) Ws[i] = W1[i];
    float2 bb = ((const float2*)b1)[lane];
    __syncthreads();

    const float2* x2 = (const float2*)xin;
    float2*       y2 = (float2*)g_y;
    const float2* Wp = (const float2*)Ws;

    float s0 = 0.f, s1 = 0.f, q0 = 0.f, q1 = 0.f;

    for (int row = blockIdx.x * WPB + w; row < N_NODES; row += NB * WPB) {
        float2 acc = x2[row * 32 + lane];
        float2 acc2 = make_float2(0.f, 0.f);
        int beg = g_rowstart[row], end = g_rowstart[row + 1];
        int e = beg;
        for (; e + 1 < end; e += 2) {
            int sa = g_esrc[e], sb = g_esrc[e + 1];
            float2 va = x2[sa * 32 + lane];
            float2 vb = x2[sb * 32 + lane];
            acc.x += va.x;  acc.y += va.y;
            acc2.x += vb.x; acc2.y += vb.y;
        }
        if (e < end) {
            int sa = g_esrc[e];
            float2 va = x2[sa * 32 + lane];
            acc.x += va.x; acc.y += va.y;
        }
        acc.x += acc2.x; acc.y += acc2.y;

        ((float2*)hs[w])[lane] = acc;
        __syncwarp();
        float o0 = bb.x, o1 = bb.y;
#pragma unroll
        for (int k = 0; k < D; k++) {
            float hk = hs[w][k];
            float2 wv = Wp[k * 32 + lane];
            o0 = fmaf(hk, wv.x, o0);
            o1 = fmaf(hk, wv.y, o1);
        }
        __syncwarp();
        y2[row * 32 + lane] = make_float2(o0, o1);
        s0 += o0; s1 += o1; q0 += o0 * o0; q1 += o1 * o1;
    }

    ((float2*)ssum[w])[lane] = make_float2(s0, s1);
    ((float2*)ssq[w])[lane]  = make_float2(q0, q1);
    __syncthreads();
    if (tid < D) {
        float S = 0.f, Q = 0.f;
#pragma unroll
        for (int ww = 0; ww < WPB; ww++) { S += ssum[ww][tid]; Q += ssq[ww][tid]; }
        g_partial[blockIdx.x * 128 + tid]      = S;
        g_partial[blockIdx.x * 128 + 64 + tid] = Q;
    }
}

// ---------------- K2: BN finalize -> per-column scale/shift -----------------
__global__ void bn_finalize(const float* __restrict__ g, const float* __restrict__ beta) {
    int c = threadIdx.x;
    if (c < D) {
        float S = 0.f, Q = 0.f;
        for (int b = 0; b < NB; b++) {
            S += g_partial[b * 128 + c];
            Q += g_partial[b * 128 + 64 + c];
        }
        float inv = 1.0f / (float)N_NODES;
        float mean = S * inv;
        float var  = Q * inv - mean * mean;
        float sc = g[c] * rsqrtf(var + BN_EPS);
        g_bnscale[c] = sc;
        g_bnshift[c] = beta[c] - mean * sc;
    }
}

// ---------------- K3: BN-apply + ReLU + GEMM with W2 (+b2) + ReLU -----------
__global__ void __launch_bounds__(THREADS)
gin_fused2(const float* __restrict__ W2, const float* __restrict__ b2,
           float* __restrict__ out) {
    __shared__ float Ws[D * D];
    __shared__ float hs[WPB][D];
    int tid = threadIdx.x, w = tid >> 5, lane = tid & 31;

    for (int i = tid; i < D * D; i += THREADS) Ws[i] = W2[i];
    float2 bb = ((const float2*)b2)[lane];
    float2 sc = ((const float2*)g_bnscale)[lane];
    float2 sh = ((const float2*)g_bnshift)[lane];
    __syncthreads();

    const float2* y2 = (const float2*)g_y;
    float2*       o2 = (float2*)out;
    const float2* Wp = (const float2*)Ws;

    for (int row = blockIdx.x * WPB + w; row < N_NODES; row += NB * WPB) {
        float2 v = y2[row * 32 + lane];
        float t0 = fmaxf(fmaf(v.x, sc.x, sh.x), 0.f);
        float t1 = fmaxf(fmaf(v.y, sc.y, sh.y), 0.f);
        ((float2*)hs[w])[lane] = make_float2(t0, t1);
        __syncwarp();
        float o0 = bb.x, o1 = bb.y;
#pragma unroll
        for (int k = 0; k < D; k++) {
            float hk = hs[w][k];
            float2 wv = Wp[k * 32 + lane];
            o0 = fmaf(hk, wv.x, o0);
            o1 = fmaf(hk, wv.y, o1);
        }
        __syncwarp();
        o0 = fmaxf(o0, 0.f);
        o1 = fmaxf(o1, 0.f);
        o2[row * 32 + lane] = make_float2(o0, o1);
    }
}

// ---------------- launch -----------------------------------------------------
extern "C" void kernel_launch(void* const* d_in, const int* in_sizes, int n_in,
                              void* d_out, int out_size) {
    const float* x     = (const float*)d_in[0];
    const void*  ei    = d_in[1];
    const float* W1_0  = (const float*)d_in[2];
    const float* b1_0  = (const float*)d_in[3];
    const float* g_0   = (const float*)d_in[4];
    const float* be_0  = (const float*)d_in[5];
    const float* W2_0  = (const float*)d_in[6];
    const float* b2_0  = (const float*)d_in[7];
    const float* W1_1  = (const float*)d_in[8];
    const float* b1_1  = (const float*)d_in[9];
    const float* g_1   = (const float*)d_in[10];
    const float* be_1  = (const float*)d_in[11];
    const float* W2_1  = (const float*)d_in[12];
    const float* b2_1  = (const float*)d_in[13];

    float* out = (float*)d_out;
    float* h1  = out;
    float* h2  = out + (size_t)N_NODES * D;

    // CSR build (shared by both layers)
    detect_idx_kernel<<<1, 256>>>(ei);
    zero_deg_kernel<<<(N_NODES + 1 + 255) / 256, 256>>>();
    hist_kernel<<<1024, 256>>>(ei);
    scan_kernel<<<1, 1024>>>();
    scatter_kernel<<<1024, 256>>>(ei);

    // Layer 0
    gin_fused1<<<NB, THREADS>>>(x, W1_0, b1_0);
    bn_finalize<<<1, 64>>>(g_0, be_0);
    gin_fused2<<<NB, THREADS>>>(W2_0, b2_0, h1);

    // Layer 1 (input = h1)
    gin_fused1<<<NB, THREADS>>>(h1, W1_1, b1_1);
    bn_finalize<<<1, 64>>>(g_1, be_1);
    gin_fused2<<<NB, THREADS>>>(W2_1, b2_1, h2);
}

// round 3
// speedup vs baseline: 1.6880x; 1.6880x over previous
#include <cuda_runtime.h>

#define N_NODES 50000
#define N_EDGES 800000
#define D 64
#define BN_EPS 1e-5f
#define NB 1184              // grid size for fused kernels (148 SMs * 8)
#define WPB 8                // warps per block
#define THREADS 256
#define SCAN_B 49            // 49 blocks * 1024 = 50176 >= N_NODES

typedef unsigned long long ull;

// packed f32x2 helpers (sm_103a FFMA2 path)
#define FMA2(o, a, b, c) asm("fma.rn.f32x2 %0, %1, %2, %3;" : "=l"(o) : "l"(a), "l"(b), "l"(c))
#define ADD2(o, a, b)    asm("add.rn.f32x2 %0, %1, %2;"     : "=l"(o) : "l"(a), "l"(b))
#define PACK2(o, lo, hi) asm("mov.b64 %0, {%1, %2};"        : "=l"(o) : "r"(lo), "r"(hi))
#define UNPK2(lo, hi, i) asm("mov.b64 {%0, %1}, %2;"        : "=r"(lo), "=r"(hi) : "l"(i))

// ---------------- scratch (static device allocations; no cudaMalloc) --------
__device__ int   g_i64;                    // 1 if edge_index is int64
__device__ int   g_rowstart[N_NODES + 1];  // CSR row offsets (keyed by dst)
__device__ int   g_cursor[N_NODES];        // scatter cursors
__device__ int   g_esrc[N_EDGES];          // CSR column indices (src nodes)
__device__ float g_y[N_NODES * D];         // pre-BN GEMM1 output
__device__ float g_partial[NB * 128];      // per-block [sum(64) | sumsq(64)]
__device__ int   g_blocksum[SCAN_B];
__device__ int   g_blockoff[SCAN_B];
__device__ __align__(16) float g_bnscale[D];
__device__ __align__(16) float g_bnshift[D];

// ---------------- init: zero degrees + detect edge_index dtype --------------
// If data is int64, every value < 50000 => every odd 32-bit word is 0.
__global__ void init_kernel(const void* ei) {
    int stride = gridDim.x * blockDim.x;
    for (int i = blockIdx.x * blockDim.x + threadIdx.x; i <= N_NODES; i += stride)
        g_rowstart[i] = 0;
    if (blockIdx.x == 0) {
        __shared__ int any_nonzero;
        if (threadIdx.x == 0) any_nonzero = 0;
        __syncthreads();
        const int* w = (const int*)ei;
        for (int i = threadIdx.x; i < 1024; i += blockDim.x)
            if (w[2 * i + 1] != 0) any_nonzero = 1;
        __syncthreads();
        if (threadIdx.x == 0) g_i64 = (any_nonzero == 0) ? 1 : 0;
    }
}

__global__ void hist_kernel(const void* ei) {
    const bool i64 = (g_i64 != 0);
    const long long* p64 = (const long long*)ei;
    const int*       p32 = (const int*)ei;
    int stride = gridDim.x * blockDim.x;
    for (int e = blockIdx.x * blockDim.x + threadIdx.x; e < N_EDGES; e += stride) {
        int d = i64 ? (int)p64[N_EDGES + e] : p32[N_EDGES + e];
        atomicAdd(&g_rowstart[d], 1);
    }
}

// ---------------- multi-block scan (3 tiny kernels) -------------------------
__global__ void scan_part1() {     // SCAN_B blocks x 1024: block sums
    __shared__ int wsum[32];
    int tid = threadIdx.x, lane = tid & 31, w = tid >> 5;
    int i = blockIdx.x * 1024 + tid;
    int v = (i < N_NODES) ? g_rowstart[i] : 0;
#pragma unroll
    for (int off = 16; off > 0; off >>= 1) v += __shfl_down_sync(~0u, v, off);
    if (lane == 0) wsum[w] = v;
    __syncthreads();
    if (w == 0) {
        int s = wsum[lane];
#pragma unroll
        for (int off = 16; off > 0; off >>= 1) s += __shfl_down_sync(~0u, s, off);
        if (lane == 0) g_blocksum[blockIdx.x] = s;
    }
}

__global__ void scan_part2() {     // 1 block x 64: scan SCAN_B block sums
    __shared__ int sm[64];
    int tid = threadIdx.x;
    int v = (tid < SCAN_B) ? g_blocksum[tid] : 0;
    sm[tid] = v;
    __syncthreads();
#pragma unroll
    for (int off = 1; off < 64; off <<= 1) {
        int add = (tid >= off) ? sm[tid - off] : 0;
        __syncthreads();
        sm[tid] += add;
        __syncthreads();
    }
    if (tid < SCAN_B) g_blockoff[tid] = sm[tid] - v;   // exclusive
    if (tid == SCAN_B - 1) g_rowstart[N_NODES] = sm[tid];
}

__global__ void scan_part3() {     // SCAN_B blocks x 1024: local scan + offset
    __shared__ int wsum[32];
    int tid = threadIdx.x, lane = tid & 31, w = tid >> 5;
    int i = blockIdx.x * 1024 + tid;
    int v = (i < N_NODES) ? g_rowstart[i] : 0;
    int inc = v;
#pragma unroll
    for (int off = 1; off < 32; off <<= 1) {
        int n = __shfl_up_sync(~0u, inc, off);
        if (lane >= off) inc += n;
    }
    if (lane == 31) wsum[w] = inc;
    __syncthreads();
    if (w == 0) {
        int s = wsum[lane];
#pragma unroll
        for (int off = 1; off < 32; off <<= 1) {
            int n = __shfl_up_sync(~0u, s, off);
            if (lane >= off) s += n;
        }
        wsum[lane] = s;
    }
    __syncthreads();
    int warpoff = (w == 0) ? 0 : wsum[w - 1];
    int excl = g_blockoff[blockIdx.x] + warpoff + inc - v;
    if (i < N_NODES) { g_rowstart[i] = excl; g_cursor[i] = excl; }
}

__global__ void scatter_kernel(const void* ei) {
    const bool i64 = (g_i64 != 0);
    const long long* p64 = (const long long*)ei;
    const int*       p32 = (const int*)ei;
    int stride = gridDim.x * blockDim.x;
    for (int e = blockIdx.x * blockDim.x + threadIdx.x; e < N_EDGES; e += stride) {
        int d = i64 ? (int)p64[N_EDGES + e] : p32[N_EDGES + e];
        int s = i64 ? (int)p64[e]           : p32[e];
        int pos = atomicAdd(&g_cursor[d], 1);
        g_esrc[pos] = s;
    }
}

// ---------------- K1: aggregate + x, GEMM W1 (+b1), BN partial stats --------
// Warp-per-row: lane holds output columns (2*lane, 2*lane+1), packed f32x2.
__global__ void __launch_bounds__(THREADS)
gin_fused1(const float* __restrict__ xin, const float* __restrict__ W1,
           const float* __restrict__ b1) {
    __shared__ ull Ws[D * 32];       // W pairs: Ws[k*32+lane] = (W[k][2l], W[k][2l+1])
    __shared__ ull hsd[WPB][D];      // duplicated h: hsd[w][k] = (h_k, h_k)
    __shared__ float ssum[WPB][D];
    __shared__ float ssq[WPB][D];
    int tid = threadIdx.x, w = tid >> 5, lane = tid & 31;

    const ull* W1p = (const ull*)W1;
    for (int i = tid; i < D * 32; i += THREADS) Ws[i] = W1p[i];
    ull bb = ((const ull*)b1)[lane];
    __syncthreads();

    const ull* x2 = (const ull*)xin;
    ull*       y2 = (ull*)g_y;

    float s0 = 0.f, s1 = 0.f, q0 = 0.f, q1 = 0.f;

    for (int row = blockIdx.x * WPB + w; row < N_NODES; row += NB * WPB) {
        ull a0 = x2[row * 32 + lane];
        ull a1 = 0ull, a2 = 0ull, a3 = 0ull;   // (0.f,0.f) bit pattern
        int beg = g_rowstart[row], end = g_rowstart[row + 1];
        int e = beg;
        for (; e + 3 < end; e += 4) {
            int i0 = g_esrc[e], i1 = g_esrc[e + 1];
            int i2 = g_esrc[e + 2], i3 = g_esrc[e + 3];
            ull v0 = x2[i0 * 32 + lane];
            ull v1 = x2[i1 * 32 + lane];
            ull v2 = x2[i2 * 32 + lane];
            ull v3 = x2[i3 * 32 + lane];
            ADD2(a0, a0, v0); ADD2(a1, a1, v1);
            ADD2(a2, a2, v2); ADD2(a3, a3, v3);
        }
        for (; e < end; e++) {
            ull v0 = x2[g_esrc[e] * 32 + lane];
            ADD2(a0, a0, v0);
        }
        ADD2(a0, a0, a1); ADD2(a2, a2, a3); ADD2(a0, a0, a2);

        unsigned lo, hi;
        UNPK2(lo, hi, a0);
        ull dlo, dhi;
        PACK2(dlo, lo, lo); PACK2(dhi, hi, hi);
        hsd[w][2 * lane]     = dlo;
        hsd[w][2 * lane + 1] = dhi;
        __syncwarp();

        ull acc = bb;
#pragma unroll
        for (int k = 0; k < D; k++) {
            ull hk = hsd[w][k];
            ull wv = Ws[k * 32 + lane];
            FMA2(acc, hk, wv, acc);
        }
        __syncwarp();
        y2[row * 32 + lane] = acc;

        unsigned u0, u1;
        UNPK2(u0, u1, acc);
        float o0 = __uint_as_float(u0), o1 = __uint_as_float(u1);
        s0 += o0; s1 += o1; q0 += o0 * o0; q1 += o1 * o1;
    }

    ssum[w][2 * lane] = s0; ssum[w][2 * lane + 1] = s1;
    ssq[w][2 * lane]  = q0; ssq[w][2 * lane + 1]  = q1;
    __syncthreads();
    if (tid < D) {
        float S = 0.f, Q = 0.f;
#pragma unroll
        for (int ww = 0; ww < WPB; ww++) { S += ssum[ww][tid]; Q += ssq[ww][tid]; }
        g_partial[blockIdx.x * 128 + tid]      = S;
        g_partial[blockIdx.x * 128 + 64 + tid] = Q;
    }
}

// ---------------- K2: BN finalize -> per-column scale/shift -----------------
__global__ void bn_finalize(const float* __restrict__ g, const float* __restrict__ beta) {
    int c = threadIdx.x;
    if (c < D) {
        float S = 0.f, Q = 0.f;
        for (int b = 0; b < NB; b++) {
            S += g_partial[b * 128 + c];
            Q += g_partial[b * 128 + 64 + c];
        }
        float inv = 1.0f / (float)N_NODES;
        float mean = S * inv;
        float var  = Q * inv - mean * mean;
        float sc = g[c] * rsqrtf(var + BN_EPS);
        g_bnscale[c] = sc;
        g_bnshift[c] = beta[c] - mean * sc;
    }
}

// ---------------- K3: BN-apply + ReLU + GEMM W2 (+b2) + ReLU ----------------
__global__ void __launch_bounds__(THREADS)
gin_fused2(const float* __restrict__ W2, const float* __restrict__ b2,
           float* __restrict__ out) {
    __shared__ ull Ws[D * 32];
    __shared__ ull hsd[WPB][D];
    int tid = threadIdx.x, w = tid >> 5, lane = tid & 31;

    const ull* W2p = (const ull*)W2;
    for (int i = tid; i < D * 32; i += THREADS) Ws[i] = W2p[i];
    ull bb = ((const ull*)b2)[lane];
    ull sc = ((const ull*)g_bnscale)[lane];
    ull sh = ((const ull*)g_bnshift)[lane];
    __syncthreads();

    const ull* y2 = (const ull*)g_y;
    float2*    o2 = (float2*)out;

    for (int row = blockIdx.x * WPB + w; row < N_NODES; row += NB * WPB) {
        ull v = y2[row * 32 + lane];
        ull t;
        FMA2(t, v, sc, sh);
        unsigned lo, hi;
        UNPK2(lo, hi, t);
        float t0 = fmaxf(__uint_as_float(lo), 0.f);
        float t1 = fmaxf(__uint_as_float(hi), 0.f);
        ull dlo, dhi;
        PACK2(dlo, __float_as_uint(t0), __float_as_uint(t0));
        PACK2(dhi, __float_as_uint(t1), __float_as_uint(t1));
        hsd[w][2 * lane]     = dlo;
        hsd[w][2 * lane + 1] = dhi;
        __syncwarp();

        ull acc = bb;
#pragma unroll
        for (int k = 0; k < D; k++) {
            ull hk = hsd[w][k];
            ull wv = Ws[k * 32 + lane];
            FMA2(acc, hk, wv, acc);
        }
        __syncwarp();

        unsigned u0, u1;
        UNPK2(u0, u1, acc);
        float o0 = fmaxf(__uint_as_float(u0), 0.f);
        float o1 = fmaxf(__uint_as_float(u1), 0.f);
        o2[row * 32 + lane] = make_float2(o0, o1);
    }
}

// ---------------- launch -----------------------------------------------------
extern "C" void kernel_launch(void* const* d_in, const int* in_sizes, int n_in,
                              void* d_out, int out_size) {
    const float* x     = (const float*)d_in[0];
    const void*  ei    = d_in[1];
    const float* W1_0  = (const float*)d_in[2];
    const float* b1_0  = (const float*)d_in[3];
    const float* g_0   = (const float*)d_in[4];
    const float* be_0  = (const float*)d_in[5];
    const float* W2_0  = (const float*)d_in[6];
    const float* b2_0  = (const float*)d_in[7];
    const float* W1_1  = (const float*)d_in[8];
    const float* b1_1  = (const float*)d_in[9];
    const float* g_1   = (const float*)d_in[10];
    const float* be_1  = (const float*)d_in[11];
    const float* W2_1  = (const float*)d_in[12];
    const float* b2_1  = (const float*)d_in[13];

    float* out = (float*)d_out;
    float* h1  = out;
    float* h2  = out + (size_t)N_NODES * D;

    // CSR build (shared by both layers)
    init_kernel<<<208, 256>>>(ei);
    hist_kernel<<<1024, 256>>>(ei);
    scan_part1<<<SCAN_B, 1024>>>();
    scan_part2<<<1, 64>>>();
    scan_part3<<<SCAN_B, 1024>>>();
    scatter_kernel<<<1024, 256>>>(ei);

    // Layer 0
    gin_fused1<<<NB, THREADS>>>(x, W1_0, b1_0);
    bn_finalize<<<1, 64>>>(g_0, be_0);
    gin_fused2<<<NB, THREADS>>>(W2_0, b2_0, h1);

    // Layer 1 (input = h1)
    gin_fused1<<<NB, THREADS>>>(h1, W1_1, b1_1);
    bn_finalize<<<1, 64>>>(g_1, be_1);
    gin_fused2<<<NB, THREADS>>>(W2_1, b2_1, h2);
}

// round 4
// speedup vs baseline: 2.8861x; 1.7098x over previous
#include <cuda_runtime.h>

#define N_NODES 50000
#define N_EDGES 800000
#define D 64
#define BN_EPS 1e-5f
#define NB_F 592             // fused-kernel grid (148 SMs * 4 resident CTAs)
#define WPB 8                // warps per block
#define THREADS 256
#define ROWS 4               // rows per warp-group in the GEMM
#define SCAN_B 49            // 49 blocks * 1024 = 50176 >= N_NODES

typedef unsigned long long ull;

// packed f32x2 helpers (sm_103a FFMA2 path)
#define FMA2(o, a, b, c) asm("fma.rn.f32x2 %0, %1, %2, %3;" : "=l"(o) : "l"(a), "l"(b), "l"(c))
#define ADD2(o, a, b)    asm("add.rn.f32x2 %0, %1, %2;"     : "=l"(o) : "l"(a), "l"(b))
#define PACK2(o, lo, hi) asm("mov.b64 %0, {%1, %2};"        : "=l"(o) : "r"(lo), "r"(hi))
#define UNPK2(lo, hi, i) asm("mov.b64 {%0, %1}, %2;"        : "=r"(lo), "=r"(hi) : "l"(i))

// ---------------- scratch (static device allocations; no cudaMalloc) --------
__device__ int   g_i64;                    // 1 if edge_index is int64
__device__ int   g_rowstart[N_NODES + 1];  // CSR row offsets (keyed by dst)
__device__ int   g_cursor[N_NODES];        // scatter cursors
__device__ int   g_esrc[N_EDGES];          // CSR column indices (src nodes)
__device__ float g_y[N_NODES * D];         // pre-BN GEMM1 output
__device__ float g_partial[NB_F * 128];    // per-block [sum(64) | sumsq(64)]
__device__ int   g_blocksum[SCAN_B];
__device__ __align__(16) float g_bnscale[D];
__device__ __align__(16) float g_bnshift[D];

// ---------------- init: zero degrees + detect edge_index dtype --------------
// If data is int64, every value < 50000 => every odd 32-bit word is 0.
__global__ void init_kernel(const void* ei) {
    int stride = gridDim.x * blockDim.x;
    for (int i = blockIdx.x * blockDim.x + threadIdx.x; i < N_NODES; i += stride)
        g_rowstart[i] = 0;
    if (blockIdx.x == 0) {
        __shared__ int any_nonzero;
        if (threadIdx.x == 0) { any_nonzero = 0; g_rowstart[N_NODES] = N_EDGES; }
        __syncthreads();
        const int* w = (const int*)ei;
        for (int i = threadIdx.x; i < 1024; i += blockDim.x)
            if (w[2 * i + 1] != 0) any_nonzero = 1;
        __syncthreads();
        if (threadIdx.x == 0) g_i64 = (any_nonzero == 0) ? 1 : 0;
    }
}

__global__ void hist_kernel(const void* ei) {
    const bool i64 = (g_i64 != 0);
    const long long* p64 = (const long long*)ei;
    const int*       p32 = (const int*)ei;
    int stride = gridDim.x * blockDim.x;
    for (int e = blockIdx.x * blockDim.x + threadIdx.x; e < N_EDGES; e += stride) {
        int d = i64 ? (int)p64[N_EDGES + e] : p32[N_EDGES + e];
        atomicAdd(&g_rowstart[d], 1);
    }
}

// ---------------- scan: 2 kernels ------------------------------------------
__global__ void scan_part1() {     // SCAN_B blocks x 1024: block sums
    __shared__ int wsum[32];
    int tid = threadIdx.x, lane = tid & 31, w = tid >> 5;
    int i = blockIdx.x * 1024 + tid;
    int v = (i < N_NODES) ? g_rowstart[i] : 0;
#pragma unroll
    for (int off = 16; off > 0; off >>= 1) v += __shfl_down_sync(~0u, v, off);
    if (lane == 0) wsum[w] = v;
    __syncthreads();
    if (w == 0) {
        int s = wsum[lane];
#pragma unroll
        for (int off = 16; off > 0; off >>= 1) s += __shfl_down_sync(~0u, s, off);
        if (lane == 0) g_blocksum[blockIdx.x] = s;
    }
}

__global__ void scan_part23() {    // SCAN_B blocks x 1024: local scan + offsets
    __shared__ int wsum[32];
    __shared__ int sbs[64];
    __shared__ int blockoff_s;
    int tid = threadIdx.x, lane = tid & 31, w = tid >> 5;
    if (tid < 64) sbs[tid] = (tid < SCAN_B) ? g_blocksum[tid] : 0;

    int i = blockIdx.x * 1024 + tid;
    int v = (i < N_NODES) ? g_rowstart[i] : 0;
    int inc = v;
#pragma unroll
    for (int off = 1; off < 32; off <<= 1) {
        int n = __shfl_up_sync(~0u, inc, off);
        if (lane >= off) inc += n;
    }
    if (lane == 31) wsum[w] = inc;
    __syncthreads();
    if (w == 0) {
        int s = wsum[lane];
#pragma unroll
        for (int off = 1; off < 32; off <<= 1) {
            int n = __shfl_up_sync(~0u, s, off);
            if (lane >= off) s += n;
        }
        wsum[lane] = s;
    }
    if (tid == 32) {   // warp 1: serial prefix over 49 smem values (~200 cyc)
        int off = 0;
        for (int j = 0; j < blockIdx.x; j++) off += sbs[j];
        blockoff_s = off;
    }
    __syncthreads();
    int warpoff = (w == 0) ? 0 : wsum[w - 1];
    int excl = blockoff_s + warpoff + inc - v;
    if (i < N_NODES) { g_rowstart[i] = excl; g_cursor[i] = excl; }
}

__global__ void scatter_kernel(const void* ei) {
    const bool i64 = (g_i64 != 0);
    const long long* p64 = (const long long*)ei;
    const int*       p32 = (const int*)ei;
    int stride = gridDim.x * blockDim.x;
    for (int e = blockIdx.x * blockDim.x + threadIdx.x; e < N_EDGES; e += stride) {
        int d = i64 ? (int)p64[N_EDGES + e] : p32[N_EDGES + e];
        int s = i64 ? (int)p64[e]           : p32[e];
        int pos = atomicAdd(&g_cursor[d], 1);
        g_esrc[pos] = s;
    }
}

// ---- shared GEMM core: 4 rows per warp, h in registers, shuffle broadcast --
// lane l holds h[2l] (ax) and h[2l+1] (ay) per row. acc[r] = packed out pair.
__device__ __forceinline__ void warp_gemm4(const ull* __restrict__ Ws, ull bb,
                                           const float* ax, const float* ay,
                                           ull* acc, int lane) {
    acc[0] = bb; acc[1] = bb; acc[2] = bb; acc[3] = bb;
#pragma unroll
    for (int k = 0; k < D; k++) {
        ull wv = Ws[k * 32 + lane];
#pragma unroll
        for (int r = 0; r < ROWS; r++) {
            float hv = __shfl_sync(~0u, (k & 1) ? ay[r] : ax[r], k >> 1);
            unsigned hu = __float_as_uint(hv);
            ull h2; PACK2(h2, hu, hu);
            FMA2(acc[r], h2, wv, acc[r]);
        }
    }
}

// ---------------- K1: aggregate + x, GEMM W1 (+b1), BN partial stats --------
__global__ void __launch_bounds__(THREADS)
gin_fused1(const float* __restrict__ xin, const float* __restrict__ W1,
           const float* __restrict__ b1) {
    __shared__ ull Ws[D * 32];       // Ws[k*32+lane] = (W[k][2l], W[k][2l+1])
    __shared__ float ssum[WPB][D];
    __shared__ float ssq[WPB][D];
    int tid = threadIdx.x, w = tid >> 5, lane = tid & 31;

    const ull* W1p = (const ull*)W1;
    for (int i = tid; i < D * 32; i += THREADS) Ws[i] = W1p[i];
    ull bb = ((const ull*)b1)[lane];
    __syncthreads();

    const ull* x2 = (const ull*)xin;
    ull*       y2 = (ull*)g_y;

    float s0 = 0.f, s1 = 0.f, q0 = 0.f, q1 = 0.f;
    int gid0 = blockIdx.x * WPB + w;          // warp-group id
    const int GSTRIDE = NB_F * WPB;           // 4736
    const int NGROUPS = N_NODES / ROWS;       // 12500

    for (int gid = gid0; gid < NGROUPS; gid += GSTRIDE) {
        int row0 = gid * ROWS;
        float ax[ROWS], ay[ROWS];
#pragma unroll
        for (int r = 0; r < ROWS; r++) {
            int row = row0 + r;
            ull a0 = x2[row * 32 + lane];
            ull a1 = 0ull, a2 = 0ull, a3 = 0ull;
            int beg = g_rowstart[row], end = g_rowstart[row + 1];
            int e = beg;
            for (; e + 3 < end; e += 4) {
                int i0 = g_esrc[e], i1 = g_esrc[e + 1];
                int i2 = g_esrc[e + 2], i3 = g_esrc[e + 3];
                ull v0 = x2[i0 * 32 + lane];
                ull v1 = x2[i1 * 32 + lane];
                ull v2 = x2[i2 * 32 + lane];
                ull v3 = x2[i3 * 32 + lane];
                ADD2(a0, a0, v0); ADD2(a1, a1, v1);
                ADD2(a2, a2, v2); ADD2(a3, a3, v3);
            }
            for (; e < end; e++) {
                ull v0 = x2[g_esrc[e] * 32 + lane];
                ADD2(a0, a0, v0);
            }
            ADD2(a0, a0, a1); ADD2(a2, a2, a3); ADD2(a0, a0, a2);
            unsigned lo, hi; UNPK2(lo, hi, a0);
            ax[r] = __uint_as_float(lo); ay[r] = __uint_as_float(hi);
        }

        ull acc[ROWS];
        warp_gemm4(Ws, bb, ax, ay, acc, lane);

#pragma unroll
        for (int r = 0; r < ROWS; r++) {
            y2[(row0 + r) * 32 + lane] = acc[r];
            unsigned u0, u1; UNPK2(u0, u1, acc[r]);
            float o0 = __uint_as_float(u0), o1 = __uint_as_float(u1);
            s0 += o0; s1 += o1; q0 += o0 * o0; q1 += o1 * o1;
        }
    }

    ssum[w][2 * lane] = s0; ssum[w][2 * lane + 1] = s1;
    ssq[w][2 * lane]  = q0; ssq[w][2 * lane + 1]  = q1;
    __syncthreads();
    if (tid < D) {
        float S = 0.f, Q = 0.f;
#pragma unroll
        for (int ww = 0; ww < WPB; ww++) { S += ssum[ww][tid]; Q += ssq[ww][tid]; }
        g_partial[blockIdx.x * 128 + tid]      = S;
        g_partial[blockIdx.x * 128 + 64 + tid] = Q;
    }
}

// ---------------- K2: BN finalize -> per-column scale/shift -----------------
__global__ void bn_finalize(const float* __restrict__ g, const float* __restrict__ beta) {
    __shared__ float sS[8][D], sQ[8][D];
    int c = threadIdx.x & 63, ch = threadIdx.x >> 6;   // 512 threads
    float S = 0.f, Q = 0.f;
    for (int b = ch; b < NB_F; b += 8) {
        S += g_partial[b * 128 + c];
        Q += g_partial[b * 128 + 64 + c];
    }
    sS[ch][c] = S; sQ[ch][c] = Q;
    __syncthreads();
    if (threadIdx.x < D) {
        float St = 0.f, Qt = 0.f;
#pragma unroll
        for (int k = 0; k < 8; k++) { St += sS[k][c]; Qt += sQ[k][c]; }
        float inv = 1.0f / (float)N_NODES;
        float mean = St * inv;
        float var  = Qt * inv - mean * mean;
        float sc = g[c] * rsqrtf(var + BN_EPS);
        g_bnscale[c] = sc;
        g_bnshift[c] = beta[c] - mean * sc;
    }
}

// ---------------- K3: BN-apply + ReLU + GEMM W2 (+b2) + ReLU ----------------
__global__ void __launch_bounds__(THREADS)
gin_fused2(const float* __restrict__ W2, const float* __restrict__ b2,
           float* __restrict__ out) {
    __shared__ ull Ws[D * 32];
    int tid = threadIdx.x, w = tid >> 5, lane = tid & 31;

    const ull* W2p = (const ull*)W2;
    for (int i = tid; i < D * 32; i += THREADS) Ws[i] = W2p[i];
    ull bb = ((const ull*)b2)[lane];
    ull sc = ((const ull*)g_bnscale)[lane];
    ull sh = ((const ull*)g_bnshift)[lane];
    __syncthreads();

    const ull* y2 = (const ull*)g_y;
    float2*    o2 = (float2*)out;

    int gid0 = blockIdx.x * WPB + w;
    const int GSTRIDE = NB_F * WPB;
    const int NGROUPS = N_NODES / ROWS;

    for (int gid = gid0; gid < NGROUPS; gid += GSTRIDE) {
        int row0 = gid * ROWS;
        float ax[ROWS], ay[ROWS];
#pragma unroll
        for (int r = 0; r < ROWS; r++) {
            ull v = y2[(row0 + r) * 32 + lane];
            ull t; FMA2(t, v, sc, sh);
            unsigned lo, hi; UNPK2(lo, hi, t);
            ax[r] = fmaxf(__uint_as_float(lo), 0.f);
            ay[r] = fmaxf(__uint_as_float(hi), 0.f);
        }

        ull acc[ROWS];
        warp_gemm4(Ws, bb, ax, ay, acc, lane);

#pragma unroll
        for (int r = 0; r < ROWS; r++) {
            unsigned u0, u1; UNPK2(u0, u1, acc[r]);
            float o0 = fmaxf(__uint_as_float(u0), 0.f);
            float o1 = fmaxf(__uint_as_float(u1), 0.f);
            o2[(row0 + r) * 32 + lane] = make_float2(o0, o1);
        }
    }
}

// ---------------- launch -----------------------------------------------------
extern "C" void kernel_launch(void* const* d_in, const int* in_sizes, int n_in,
                              void* d_out, int out_size) {
    const float* x     = (const float*)d_in[0];
    const void*  ei    = d_in[1];
    const float* W1_0  = (const float*)d_in[2];
    const float* b1_0  = (const float*)d_in[3];
    const float* g_0   = (const float*)d_in[4];
    const float* be_0  = (const float*)d_in[5];
    const float* W2_0  = (const float*)d_in[6];
    const float* b2_0  = (const float*)d_in[7];
    const float* W1_1  = (const float*)d_in[8];
    const float* b1_1  = (const float*)d_in[9];
    const float* g_1   = (const float*)d_in[10];
    const float* be_1  = (const float*)d_in[11];
    const float* W2_1  = (const float*)d_in[12];
    const float* b2_1  = (const float*)d_in[13];

    float* out = (float*)d_out;
    float* h1  = out;
    float* h2  = out + (size_t)N_NODES * D;

    // CSR build (shared by both layers)
    init_kernel<<<208, 256>>>(ei);
    hist_kernel<<<1024, 256>>>(ei);
    scan_part1<<<SCAN_B, 1024>>>();
    scan_part23<<<SCAN_B, 1024>>>();
    scatter_kernel<<<1024, 256>>>(ei);

    // Layer 0
    gin_fused1<<<NB_F, THREADS>>>(x, W1_0, b1_0);
    bn_finalize<<<1, 512>>>(g_0, be_0);
    gin_fused2<<<NB_F, THREADS>>>(W2_0, b2_0, h1);

    // Layer 1 (input = h1)
    gin_fused1<<<NB_F, THREADS>>>(h1, W1_1, b1_1);
    bn_finalize<<<1, 512>>>(g_1, be_1);
    gin_fused2<<<NB_F, THREADS>>>(W2_1, b2_1, h2);
}

// round 5
// speedup vs baseline: 3.0040x; 1.0409x over previous
#include <cuda_runtime.h>
#include <cuda_fp16.h>

#define N_NODES 50000
#define N_EDGES 800000
#define D 64
#define BN_EPS 1e-5f
#define NB_F 592             // fused-kernel grid (148 SMs * 4)
#define WPB 8
#define THREADS 256
#define ROWS 4               // rows per warp in the GEMM
#define HS_B 592             // hist_scan_scatter grid (must be all-resident)
#define SCAN_BLK 196         // 196*256 = 50176 >= N_NODES
#define MAXE 6               // ceil(N_EDGES / (HS_B*256))

typedef unsigned long long ull;

// packed f32x2 helpers (sm_103a FFMA2 path)
#define FMA2(o, a, b, c) asm("fma.rn.f32x2 %0, %1, %2, %3;" : "=l"(o) : "l"(a), "l"(b), "l"(c))
#define ADD2(o, a, b)    asm("add.rn.f32x2 %0, %1, %2;"     : "=l"(o) : "l"(a), "l"(b))
#define PACK2(o, lo, hi) asm("mov.b64 %0, {%1, %2};"        : "=l"(o) : "r"(lo), "r"(hi))
#define UNPK2(lo, hi, i) asm("mov.b64 {%0, %1}, %2;"        : "=r"(lo), "=r"(hi) : "l"(i))

// ---------------- scratch (static device allocations; no cudaMalloc) --------
__device__ int      g_i64;
__device__ int      g_rowstart[N_NODES + 1];
__device__ int      g_cursor[N_NODES];
__device__ int      g_esrc[N_EDGES];
__device__ float    g_y[N_NODES * D];          // pre-BN GEMM1 output
__device__ float    g_partial[NB_F * 128];     // per-block [sum(64)|sumsq(64)]
__device__ int      g_blocksum[SCAN_BLK];
__device__ unsigned g_bar[4];                  // grid-barrier counters
__device__ __half2  g_g16[N_NODES * 32];       // fp16 copy of gather source
__device__ __align__(16) float g_bnscale[D];
__device__ __align__(16) float g_bnshift[D];

// ---------------- init: zero state + detect edge_index dtype ----------------
__global__ void init_kernel(const void* ei) {
    int stride = gridDim.x * blockDim.x;
    int gt = blockIdx.x * blockDim.x + threadIdx.x;
    for (int i = gt; i < N_NODES; i += stride) g_rowstart[i] = 0;
    if (gt < 4) g_bar[gt] = 0;
    if (blockIdx.x == 0) {
        __shared__ int any_nonzero;
        if (threadIdx.x == 0) { any_nonzero = 0; g_rowstart[N_NODES] = N_EDGES; }
        __syncthreads();
        const int* w = (const int*)ei;
        for (int i = threadIdx.x; i < 1024; i += blockDim.x)
            if (w[2 * i + 1] != 0) any_nonzero = 1;
        __syncthreads();
        if (threadIdx.x == 0) g_i64 = (any_nonzero == 0) ? 1 : 0;
    }
}

// ---------------- grid barrier (all HS_B CTAs resident) ---------------------
__device__ __forceinline__ void grid_bar(unsigned* ctr) {
    __syncthreads();
    if (threadIdx.x == 0) {
        __threadfence();
        atomicAdd(ctr, 1u);
        while (atomicAdd(ctr, 0u) < (unsigned)HS_B) { }
    }
    __syncthreads();
    __threadfence();
}

// ---------------- hist + scan + scatter: one persistent kernel --------------
__global__ void __launch_bounds__(256, 4) hist_scan_scatter(const void* ei) {
    const bool i64 = (g_i64 != 0);
    const int* p32 = (const int*)ei;
    int tid = threadIdx.x, b = blockIdx.x;
    const int gstride = HS_B * 256;
    int gt = b * 256 + tid;

    // phase 1: histogram of dst (cache dst in registers for phase 4)
    int dcache[MAXE];
#pragma unroll
    for (int k = 0; k < MAXE; k++) {
        int e = gt + k * gstride;
        if (e < N_EDGES) {
            int d = i64 ? p32[2 * (N_EDGES + e)] : p32[N_EDGES + e];
            dcache[k] = d;
            atomicAdd(&g_rowstart[d], 1);
        }
    }
    grid_bar(&g_bar[0]);

    // phase 2: per-block local scan of 256 degrees + publish block sum
    __shared__ int wsum[8];
    __shared__ int sbs[SCAN_BLK];
    __shared__ int blockoff_s;
    int excl_local = 0;
    if (b < SCAN_BLK) {
        int i = b * 256 + tid;
        int v = (i < N_NODES) ? g_rowstart[i] : 0;
        int lane = tid & 31, w = tid >> 5;
        int inc = v;
#pragma unroll
        for (int off = 1; off < 32; off <<= 1) {
            int n = __shfl_up_sync(~0u, inc, off);
            if (lane >= off) inc += n;
        }
        if (lane == 31) wsum[w] = inc;
        __syncthreads();
        if (w == 0) {
            int s = (lane < 8) ? wsum[lane] : 0;
#pragma unroll
            for (int off = 1; off < 8; off <<= 1) {
                int n = __shfl_up_sync(~0u, s, off);
                if (lane >= off) s += n;
            }
            if (lane < 8) wsum[lane] = s;
        }
        __syncthreads();
        int warpoff = (w == 0) ? 0 : wsum[w - 1];
        excl_local = warpoff + inc - v;
        if (tid == 0) g_blocksum[b] = wsum[7];
    }
    grid_bar(&g_bar[1]);

    // phase 3: lookback offset + write rowstart/cursor
    if (b < SCAN_BLK) {
        for (int j = tid; j < SCAN_BLK; j += 256) sbs[j] = g_blocksum[j];
        __syncthreads();
        if (tid == 0) {
            int o = 0;
            for (int j = 0; j < b; j++) o += sbs[j];
            blockoff_s = o;
        }
        __syncthreads();
        int i = b * 256 + tid;
        if (i < N_NODES) {
            int e0 = blockoff_s + excl_local;
            g_rowstart[i] = e0;
            g_cursor[i]   = e0;
        }
    }
    grid_bar(&g_bar[2]);

    // phase 4: scatter src ids into CSR order
#pragma unroll
    for (int k = 0; k < MAXE; k++) {
        int e = gt + k * gstride;
        if (e < N_EDGES) {
            int s = i64 ? p32[2 * e] : p32[e];
            int pos = atomicAdd(&g_cursor[dcache[k]], 1);
            g_esrc[pos] = s;
        }
    }
}

// ---------------- fp16 conversion of gather source --------------------------
__global__ void cvt16_kernel(const float* __restrict__ src) {
    const float2* s2 = (const float2*)src;
    int stride = gridDim.x * blockDim.x;
    for (int i = blockIdx.x * blockDim.x + threadIdx.x; i < N_NODES * 32; i += stride)
        g_g16[i] = __float22half2_rn(s2[i]);
}

// ---- shared GEMM core: 4 rows per warp, h in registers, shuffle broadcast --
__device__ __forceinline__ void warp_gemm4(const ull* __restrict__ Ws, ull bb,
                                           const float* ax, const float* ay,
                                           ull* acc, int lane) {
    acc[0] = bb; acc[1] = bb; acc[2] = bb; acc[3] = bb;
#pragma unroll
    for (int k = 0; k < D; k++) {
        ull wv = Ws[k * 32 + lane];
#pragma unroll
        for (int r = 0; r < ROWS; r++) {
            float hv = __shfl_sync(~0u, (k & 1) ? ay[r] : ax[r], k >> 1);
            unsigned hu = __float_as_uint(hv);
            ull h2; PACK2(h2, hu, hu);
            FMA2(acc[r], h2, wv, acc[r]);
        }
    }
}

// ---------------- K1: aggregate(fp16 gather) + GEMM W1 + BN partials --------
__global__ void __launch_bounds__(THREADS)
gin_fused1(const float* __restrict__ xin, const float* __restrict__ W1,
           const float* __restrict__ b1) {
    __shared__ ull Ws[D * 32];
    __shared__ float ssum[WPB][D];
    __shared__ float ssq[WPB][D];
    int tid = threadIdx.x, w = tid >> 5, lane = tid & 31;

    const ull* W1p = (const ull*)W1;
    for (int i = tid; i < D * 32; i += THREADS) Ws[i] = W1p[i];
    ull bb = ((const ull*)b1)[lane];
    __syncthreads();

    const ull*     x2  = (const ull*)xin;
    const __half2* x16 = g_g16;
    ull*           y2  = (ull*)g_y;

    float s0 = 0.f, s1 = 0.f, q0 = 0.f, q1 = 0.f;
    int gid0 = blockIdx.x * WPB + w;
    const int GSTRIDE = NB_F * WPB;
    const int NGROUPS = N_NODES / ROWS;

    for (int gid = gid0; gid < NGROUPS; gid += GSTRIDE) {
        int row0 = gid * ROWS;
        float ax[ROWS], ay[ROWS];
#pragma unroll
        for (int r = 0; r < ROWS; r++) {
            int row = row0 + r;
            ull a0 = x2[row * 32 + lane];   // self term, fp32 exact
            ull a1 = 0ull, a2 = 0ull, a3 = 0ull;
            int beg = g_rowstart[row], end = g_rowstart[row + 1];
            int e = beg;
            for (; e + 3 < end; e += 4) {
                int i0 = g_esrc[e], i1 = g_esrc[e + 1];
                int i2 = g_esrc[e + 2], i3 = g_esrc[e + 3];
                float2 f0 = __half22float2(x16[i0 * 32 + lane]);
                float2 f1 = __half22float2(x16[i1 * 32 + lane]);
                float2 f2 = __half22float2(x16[i2 * 32 + lane]);
                float2 f3 = __half22float2(x16[i3 * 32 + lane]);
                ull u0, u1, u2, u3;
                PACK2(u0, __float_as_uint(f0.x), __float_as_uint(f0.y));
                PACK2(u1, __float_as_uint(f1.x), __float_as_uint(f1.y));
                PACK2(u2, __float_as_uint(f2.x), __float_as_uint(f2.y));
                PACK2(u3, __float_as_uint(f3.x), __float_as_uint(f3.y));
                ADD2(a0, a0, u0); ADD2(a1, a1, u1);
                ADD2(a2, a2, u2); ADD2(a3, a3, u3);
            }
            for (; e < end; e++) {
                float2 f0 = __half22float2(x16[g_esrc[e] * 32 + lane]);
                ull u0; PACK2(u0, __float_as_uint(f0.x), __float_as_uint(f0.y));
                ADD2(a0, a0, u0);
            }
            ADD2(a0, a0, a1); ADD2(a2, a2, a3); ADD2(a0, a0, a2);
            unsigned lo, hi; UNPK2(lo, hi, a0);
            ax[r] = __uint_as_float(lo); ay[r] = __uint_as_float(hi);
        }

        ull acc[ROWS];
        warp_gemm4(Ws, bb, ax, ay, acc, lane);

#pragma unroll
        for (int r = 0; r < ROWS; r++) {
            y2[(row0 + r) * 32 + lane] = acc[r];
            unsigned u0, u1; UNPK2(u0, u1, acc[r]);
            float o0 = __uint_as_float(u0), o1 = __uint_as_float(u1);
            s0 += o0; s1 += o1; q0 += o0 * o0; q1 += o1 * o1;
        }
    }

    ssum[w][2 * lane] = s0; ssum[w][2 * lane + 1] = s1;
    ssq[w][2 * lane]  = q0; ssq[w][2 * lane + 1]  = q1;
    __syncthreads();
    if (tid < D) {
        float S = 0.f, Q = 0.f;
#pragma unroll
        for (int ww = 0; ww < WPB; ww++) { S += ssum[ww][tid]; Q += ssq[ww][tid]; }
        g_partial[blockIdx.x * 128 + tid]      = S;
        g_partial[blockIdx.x * 128 + 64 + tid] = Q;
    }
}

// ---------------- K2: BN finalize -------------------------------------------
__global__ void bn_finalize(const float* __restrict__ g, const float* __restrict__ beta) {
    __shared__ float sS[8][D], sQ[8][D];
    int c = threadIdx.x & 63, ch = threadIdx.x >> 6;
    float S = 0.f, Q = 0.f;
    for (int b = ch; b < NB_F; b += 8) {
        S += g_partial[b * 128 + c];
        Q += g_partial[b * 128 + 64 + c];
    }
    sS[ch][c] = S; sQ[ch][c] = Q;
    __syncthreads();
    if (threadIdx.x < D) {
        float St = 0.f, Qt = 0.f;
#pragma unroll
        for (int k = 0; k < 8; k++) { St += sS[k][c]; Qt += sQ[k][c]; }
        float inv = 1.0f / (float)N_NODES;
        float mean = St * inv;
        float var  = Qt * inv - mean * mean;
        float sc = g[c] * rsqrtf(var + BN_EPS);
        g_bnscale[c] = sc;
        g_bnshift[c] = beta[c] - mean * sc;
    }
}

// ---------------- K3: BN-apply + ReLU + GEMM W2 + ReLU (+fp16 copy) ---------
__global__ void __launch_bounds__(THREADS)
gin_fused2(const float* __restrict__ W2, const float* __restrict__ b2,
           float* __restrict__ out, int write16) {
    __shared__ ull Ws[D * 32];
    int tid = threadIdx.x, w = tid >> 5, lane = tid & 31;

    const ull* W2p = (const ull*)W2;
    for (int i = tid; i < D * 32; i += THREADS) Ws[i] = W2p[i];
    ull bb = ((const ull*)b2)[lane];
    ull sc = ((const ull*)g_bnscale)[lane];
    ull sh = ((const ull*)g_bnshift)[lane];
    __syncthreads();

    const ull* y2 = (const ull*)g_y;
    float2*    o2 = (float2*)out;

    int gid0 = blockIdx.x * WPB + w;
    const int GSTRIDE = NB_F * WPB;
    const int NGROUPS = N_NODES / ROWS;

    for (int gid = gid0; gid < NGROUPS; gid += GSTRIDE) {
        int row0 = gid * ROWS;
        float ax[ROWS], ay[ROWS];
#pragma unroll
        for (int r = 0; r < ROWS; r++) {
            ull v = y2[(row0 + r) * 32 + lane];
            ull t; FMA2(t, v, sc, sh);
            unsigned lo, hi; UNPK2(lo, hi, t);
            ax[r] = fmaxf(__uint_as_float(lo), 0.f);
            ay[r] = fmaxf(__uint_as_float(hi), 0.f);
        }

        ull acc[ROWS];
        warp_gemm4(Ws, bb, ax, ay, acc, lane);

#pragma unroll
        for (int r = 0; r < ROWS; r++) {
            unsigned u0, u1; UNPK2(u0, u1, acc[r]);
            float o0 = fmaxf(__uint_as_float(u0), 0.f);
            float o1 = fmaxf(__uint_as_float(u1), 0.f);
            o2[(row0 + r) * 32 + lane] = make_float2(o0, o1);
            if (write16)
                g_g16[(row0 + r) * 32 + lane] = __floats2half2_rn(o0, o1);
        }
    }
}

// ---------------- launch -----------------------------------------------------
extern "C" void kernel_launch(void* const* d_in, const int* in_sizes, int n_in,
                              void* d_out, int out_size) {
    const float* x     = (const float*)d_in[0];
    const void*  ei    = d_in[1];
    const float* W1_0  = (const float*)d_in[2];
    const float* b1_0  = (const float*)d_in[3];
    const float* g_0   = (const float*)d_in[4];
    const float* be_0  = (const float*)d_in[5];
    const float* W2_0  = (const float*)d_in[6];
    const float* b2_0  = (const float*)d_in[7];
    const float* W1_1  = (const float*)d_in[8];
    const float* b1_1  = (const float*)d_in[9];
    const float* g_1   = (const float*)d_in[10];
    const float* be_1  = (const float*)d_in[11];
    const float* W2_1  = (const float*)d_in[12];
    const float* b2_1  = (const float*)d_in[13];

    float* out = (float*)d_out;
    float* h1  = out;
    float* h2  = out + (size_t)N_NODES * D;

    init_kernel<<<208, 256>>>(ei);              // 1
    hist_scan_scatter<<<HS_B, 256>>>(ei);       // 2
    cvt16_kernel<<<208, 256>>>(x);              // 3

    gin_fused1<<<NB_F, THREADS>>>(x, W1_0, b1_0);        // 4  <- profiled
    bn_finalize<<<1, 512>>>(g_0, be_0);                  // 5
    gin_fused2<<<NB_F, THREADS>>>(W2_0, b2_0, h1, 1);    // 6

    gin_fused1<<<NB_F, THREADS>>>(h1, W1_1, b1_1);       // 7
    bn_finalize<<<1, 512>>>(g_1, be_1);                  // 8
    gin_fused2<<<NB_F, THREADS>>>(W2_1, b2_1, h2, 0);    // 9
}